// round 10
// baseline (speedup 1.0000x reference)
#include <cuda_runtime.h>
#include <cstdint>

#define ROWS            128
#define ROW_N           262144                     // 256*32*32
#define BLOCKS_PER_ROW  32
#define SEG_N           (ROW_N / BLOCKS_PER_ROW)   // 8192 elements per block
#define THREADS         256
#define WARPS           (THREADS / 32)             // 8
#define VEC             (SEG_N / 4 / THREADS)      // 8 float4 per thread
#define GROUPS          (VEC / 2)                  // 4 groups of 8 elements
#define TOPK            5
#define GSIZE           8
#define CAND_PER_ROW    (BLOCKS_PER_ROW * WARPS * TOPK)   // 1280 group candidates

#define FULLMASK 0xFFFFFFFFu

// Scratch (no cudaMalloc allowed). Zero-initialized device globals.
__device__ float g_cand_val[ROWS * CAND_PER_ROW];   // group max
__device__ int   g_cand_idx[ROWS * CAND_PER_ROW];   // group base index (row-relative)
__device__ int   g_row_cnt[ROWS];                   // last-block-closes-row counters

// larger value wins; equal value -> smaller index wins (jax.lax.top_k stability).
__device__ __forceinline__ bool better(float v, int i, float bv, int bi) {
    return (v > bv) || (v == bv && i < bi);
}

// Register-resident 5-way select (avoids local-memory spill from dynamic index).
__device__ __forceinline__ float get5f(const float v[TOPK], int p) {
    float r = (p == 0) ? v[0] : v[1];
    r = (p == 2) ? v[2] : r;
    r = (p == 3) ? v[3] : r;
    r = (p == 4) ? v[4] : r;
    return (p >= TOPK) ? -INFINITY : r;
}
__device__ __forceinline__ int get5i(const int v[TOPK], int p) {
    int r = (p == 0) ? v[0] : v[1];
    r = (p == 2) ? v[2] : r;
    r = (p == 3) ? v[3] : r;
    r = (p == 4) ? v[4] : r;
    return (p >= TOPK) ? 0x7fffffff : r;
}

// BRANCHLESS sorted insert (descending). Exact ties when inserted in
// increasing-index order (strict '>' keeps the earlier index).
__device__ __forceinline__ void bins5(float val, int idx, float v[TOPK], int id[TOPK]) {
    const bool p0 = val > v[0];
    const bool p1 = val > v[1];
    const bool p2 = val > v[2];
    const bool p3 = val > v[3];
    const bool p4 = val > v[4];
    v[4]  = p4 ? (p3 ? v[3]  : val) : v[4];
    id[4] = p4 ? (p3 ? id[3] : idx) : id[4];
    v[3]  = p3 ? (p2 ? v[2]  : val) : v[3];
    id[3] = p3 ? (p2 ? id[2] : idx) : id[3];
    v[2]  = p2 ? (p1 ? v[1]  : val) : v[2];
    id[2] = p2 ? (p1 ? id[1] : idx) : id[2];
    v[1]  = p1 ? (p0 ? v[0]  : val) : v[1];
    id[1] = p1 ? (p0 ? id[0] : idx) : id[1];
    v[0]  = p0 ? val  : v[0];
    id[0] = p0 ? idx  : id[0];
}

// Index-aware branchless insert (arrival order not monotone).
__device__ __forceinline__ void bins5_tie(float val, int idx, float v[TOPK], int id[TOPK]) {
    bool p[TOPK];
    #pragma unroll
    for (int j = 0; j < TOPK; ++j)
        p[j] = better(val, idx, v[j], id[j]);
    v[4]  = p[4] ? (p[3] ? v[3]  : val) : v[4];
    id[4] = p[4] ? (p[3] ? id[3] : idx) : id[4];
    v[3]  = p[3] ? (p[2] ? v[2]  : val) : v[3];
    id[3] = p[3] ? (p[2] ? id[2] : idx) : id[3];
    v[2]  = p[2] ? (p[1] ? v[1]  : val) : v[2];
    id[2] = p[2] ? (p[1] ? id[1] : idx) : id[2];
    v[1]  = p[1] ? (p[0] ? v[0]  : val) : v[1];
    id[1] = p[1] ? (p[0] ? id[0] : idx) : id[1];
    v[0]  = p[0] ? val  : v[0];
    id[0] = p[0] ? idx  : id[0];
}

// Warp argmax with index tie-break; winner broadcast to all lanes.
__device__ __forceinline__ void warp_argmax(float& cv, int& ci) {
    #pragma unroll
    for (int off = 16; off > 0; off >>= 1) {
        const float ov = __shfl_down_sync(FULLMASK, cv, off);
        const int   oi = __shfl_down_sync(FULLMASK, ci, off);
        if (better(ov, oi, cv, ci)) { cv = ov; ci = oi; }
    }
    cv = __shfl_sync(FULLMASK, cv, 0);
    ci = __shfl_sync(FULLMASK, ci, 0);
}

// Warp merge of 32 sorted 5-lists -> warp top-5. Winning lane calls emit.
template <typename EMIT>
__device__ __forceinline__ void warp_top5(const float v[TOPK], const int id[TOPK], EMIT emit) {
    int p = 0;
    #pragma unroll
    for (int r = 0; r < TOPK; ++r) {
        const float mv = get5f(v, p); const int mi = get5i(id, p);
        float cv = mv; int ci = mi;
        warp_argmax(cv, ci);
        if (mv == cv && mi == ci) {          // unique: all indices distinct
            ++p;
            emit(r, cv, ci);
        }
    }
}

// ---------------------------------------------------------------------------
// Fused kernel. Hot loop: 8 front-batched LDG.128 (MLP=8), 8 zero STG.128,
// then 4 x (7 FMNMX group-of-8 max + 1 branchless insert). Candidates are
// (groupmax, groupbase) over CONTIGUOUS 8-element groups (exactness proof
// relies on disjoint contiguous ranges). Last block of each row reduces 1280
// group candidates -> top-5 groups, re-reads those 40 elements from x, exact
// top-5 of 40, scatters 1.0.  grid = 4096, block = 256.
// ---------------------------------------------------------------------------
__global__ __launch_bounds__(THREADS)
void wta_fused(const float* __restrict__ x, float* __restrict__ out) {
    const int b    = blockIdx.x;
    const int row  = b >> 5;            // / BLOCKS_PER_ROW
    const int seg  = b & 31;            // % BLOCKS_PER_ROW
    const int t    = threadIdx.x;
    const int warp = t >> 5;
    const int lane = t & 31;

    const size_t base = (size_t)row * ROW_N + (size_t)seg * SEG_N;
    const float4* __restrict__ xv = (const float4*)(x + base);
    float4* __restrict__       ov = (float4*)(out + base);

    float v[TOPK]; int id[TOPK];
    #pragma unroll
    for (int j = 0; j < TOPK; ++j) { v[j] = -INFINITY; id[j] = 0x7fffffff; }

    // Thread t owns contiguous float4 PAIRS at 2t, 2t+1 (warp: 1024B coalesced).
    // All 8 loads issued first (MLP=8), then 8 independent zero stores.
    float4 d[VEC];
    #pragma unroll
    for (int g = 0; g < GROUPS; ++g) {
        d[2 * g]     = __ldcs(&xv[g * 2 * THREADS + 2 * t]);
        d[2 * g + 1] = __ldcs(&xv[g * 2 * THREADS + 2 * t + 1]);
    }

    const float4 z = make_float4(0.f, 0.f, 0.f, 0.f);
    #pragma unroll
    for (int g = 0; g < GROUPS; ++g) {
        __stcs(&ov[g * 2 * THREADS + 2 * t],     z);
        __stcs(&ov[g * 2 * THREADS + 2 * t + 1], z);
    }

    #pragma unroll
    for (int g = 0; g < GROUPS; ++g) {
        const float4 a = d[2 * g], c = d[2 * g + 1];
        const float gm = fmaxf(fmaxf(fmaxf(a.x, a.y), fmaxf(a.z, a.w)),
                               fmaxf(fmaxf(c.x, c.y), fmaxf(c.z, c.w)));
        const int gbase = seg * SEG_N + (g * 2 * THREADS + 2 * t) * 4;
        bins5(gm, gbase, v, id);         // one insert per 8 elements
    }

    // Warp merge -> 5 group candidates per warp straight to scratch.
    const int wbase = ((row * BLOCKS_PER_ROW + seg) * WARPS + warp) * TOPK;
    warp_top5(v, id, [&](int r, float bv, int bi) {
        g_cand_val[wbase + r] = bv;
        g_cand_idx[wbase + r] = bi;
    });

    // ---- last block of this row closes it -------------------------------
    __threadfence();                       // candidate stores -> device scope
    __shared__ int s_last;
    __syncthreads();
    if (t == 0) {
        const int old = atomicAdd(&g_row_cnt[row], 1);
        s_last = (old == BLOCKS_PER_ROW - 1);
    }
    __syncthreads();
    if (!s_last) return;
    if (t == 0) g_row_cnt[row] = 0;        // self-reset: graph-replay safe

    // Reduce this row's 1280 group candidates -> top-5 GROUPS.
    float rv[TOPK]; int ri[TOPK];
    #pragma unroll
    for (int j = 0; j < TOPK; ++j) { rv[j] = -INFINITY; ri[j] = 0x7fffffff; }

    const int cbase = row * CAND_PER_ROW;
    #pragma unroll
    for (int e = t; e < CAND_PER_ROW; e += THREADS)
        bins5_tie(__ldcg(&g_cand_val[cbase + e]),     // bypass L1: other SMs wrote
                  __ldcg(&g_cand_idx[cbase + e]), rv, ri);

    __shared__ float wv[WARPS * TOPK];
    __shared__ int   wi[WARPS * TOPK];
    __shared__ int   s_win[TOPK];
    warp_top5(rv, ri, [&](int r, float bv, int bi) {
        wv[warp * TOPK + r] = bv;
        wi[warp * TOPK + r] = bi;
    });
    __syncthreads();

    if (warp == 0) {
        float fv[TOPK]; int fi[TOPK];
        #pragma unroll
        for (int j = 0; j < TOPK; ++j) { fv[j] = -INFINITY; fi[j] = 0x7fffffff; }
        if (lane < WARPS * TOPK)
            bins5_tie(wv[lane], wi[lane], fv, fi);
        if (lane + 32 < WARPS * TOPK)
            bins5_tie(wv[lane + 32], wi[lane + 32], fv, fi);

        // Top-5 groups' base indices -> s_win.
        warp_top5(fv, fi, [&](int r, float bv, int bi) {
            s_win[r] = bi;
        });
        __syncwarp();

        // Expand the 5 winning groups: 40 elements, two slots per lane.
        const float* __restrict__ xr = x + (size_t)row * ROW_N;
        float ev0, ev1 = -INFINITY;
        int   ei0, ei1 = 0x7fffffff;
        ei0 = s_win[lane >> 3] + (lane & 7);          // lanes 0..31 -> groups 0..3
        ev0 = __ldcg(&xr[ei0]);
        if (lane < GSIZE) {                            // lanes 0..7 -> group 4
            ei1 = s_win[4] + lane;
            ev1 = __ldcg(&xr[ei1]);
        }

        // 5 rounds of warp argmax with exact tie rules; lane 0 scatters.
        #pragma unroll
        for (int r = 0; r < TOPK; ++r) {
            const bool useA = better(ev0, ei0, ev1, ei1);
            const float mv = useA ? ev0 : ev1;
            const int   mi = useA ? ei0 : ei1;
            float cv = mv; int ci = mi;
            warp_argmax(cv, ci);
            if (ci == ei0) ev0 = -INFINITY;            // remove winner (unique idx)
            if (ci == ei1) ev1 = -INFINITY;
            if (lane == 0)
                out[(size_t)row * ROW_N + ci] = 1.0f;
        }
    }
}

// ---------------------------------------------------------------------------
extern "C" void kernel_launch(void* const* d_in, const int* in_sizes, int n_in,
                              void* d_out, int out_size) {
    const float* x = (const float*)d_in[0];
    float* out = (float*)d_out;
    wta_fused<<<ROWS * BLOCKS_PER_ROW, THREADS>>>(x, out);
}